// round 15
// baseline (speedup 1.0000x reference)
#include <cuda_runtime.h>
#include <cuda_fp16.h>
#include <stdint.h>

#define NSAMP 8192
#define MAX_IN 8
#define IMG_DIM 3200
#define FC 512
#define NATTR 7
#define NANS 2
#define M1 (NSAMP * 3)
#define NROW2 (2 * NSAMP)

// Common tiling: 128x128 block, BK=32, 256 thr (8 warps = 2M x 4N of 64x32)
#define BM 128
#define BN 128
#define BK 32
#define KT1 (IMG_DIM / BK)         // 100
#define KT2 ((2 * FC) / BK)        // 32
#define ASTRIDE 40                 // fp16 elems per A smem row (80 B)
#define BSTRIDE 136                // fp16 elems per B smem row (272 B)

#define OFF_A  0
#define OFF_B  10240
#define STAGE  18944
#define NSTG   4
#define SMEM_SZ (NSTG * STAGE)     // 75776 -> 2 CTAs/SM

#define GM2 128
#define MAXCH (NSAMP / GM2 + NATTR)  // 71

// ---------------- scratch ----------------
__device__ __align__(16) __half g_af[(size_t)M1 * IMG_DIM];   // compact rows
__device__ __align__(16) __half g_wh[(size_t)IMG_DIM * FC];
__device__ __align__(16) __half g_w1h[(size_t)NATTR * 2 * FC * FC];
__device__ __align__(16) __half g_xf[(size_t)NSAMP * 2 * FC];
__device__ __align__(16) __half g_feats[(size_t)M1 * FC];
__device__ int g_counts[NATTR];
__device__ int g_offsets[NATTR];
__device__ int g_chunk_off[NATTR + 1];
__device__ int g_idx[NSAMP];
__device__ int g_row2[NSAMP];
__device__ int g_nrow;

// ---------------- helpers ----------------
__device__ __forceinline__ uint2 pack4h(float4 v) {
    __half2 a = __floats2half2_rn(v.x, v.y);
    __half2 b = __floats2half2_rn(v.z, v.w);
    uint2 r;
    r.x = *(uint32_t*)&a;
    r.y = *(uint32_t*)&b;
    return r;
}
__device__ __forceinline__ void mma16816(float* c, const uint32_t* a, const uint32_t* b) {
    asm("mma.sync.aligned.m16n8k16.row.col.f32.f16.f16.f32 "
        "{%0,%1,%2,%3}, {%4,%5,%6,%7}, {%8,%9}, {%0,%1,%2,%3};\n"
        : "+f"(c[0]), "+f"(c[1]), "+f"(c[2]), "+f"(c[3])
        : "r"(a[0]), "r"(a[1]), "r"(a[2]), "r"(a[3]), "r"(b[0]), "r"(b[1]));
}
__device__ __forceinline__ void ldsm_x4(uint32_t* r, uint32_t a) {
    asm volatile("ldmatrix.sync.aligned.m8n8.x4.shared.b16 {%0,%1,%2,%3}, [%4];"
                 : "=r"(r[0]), "=r"(r[1]), "=r"(r[2]), "=r"(r[3]) : "r"(a));
}
__device__ __forceinline__ void ldsm_x4_t(uint32_t* r, uint32_t a) {
    asm volatile("ldmatrix.sync.aligned.m8n8.x4.trans.shared.b16 {%0,%1,%2,%3}, [%4];"
                 : "=r"(r[0]), "=r"(r[1]), "=r"(r[2]), "=r"(r[3]) : "r"(a));
}
__device__ __forceinline__ void cp16(uint32_t dst, const void* src) {
    asm volatile("cp.async.cg.shared.global [%0], [%1], 16;"
                 :: "r"(dst), "l"(src) : "memory");
}
__device__ __forceinline__ void cp16z(uint32_t dst, const void* src, uint32_t sz) {
    asm volatile("cp.async.cg.shared.global [%0], [%1], 16, %2;"
                 :: "r"(dst), "l"(src), "r"(sz) : "memory");
}
__device__ __forceinline__ void cp_commit() {
    asm volatile("cp.async.commit_group;" ::: "memory");
}
__device__ __forceinline__ void cp_wait2() {
    asm volatile("cp.async.wait_group 2;" ::: "memory");
}
__device__ __forceinline__ void cp_wait1() {
    asm volatile("cp.async.wait_group 1;" ::: "memory");
}
__device__ __forceinline__ void cp_wait0() {
    asm volatile("cp.async.wait_group 0;" ::: "memory");
}

// ---------------- fused sort + output init ----------------
__global__ void k_sort(const int* __restrict__ attrs,
                       const float* __restrict__ b2,
                       float* __restrict__ out) {
    __shared__ int scnt[NATTR], scur[NATTR], soff[NATTR];
    const int t = threadIdx.x;
    if (t < NATTR) scnt[t] = 0;
    __syncthreads();
    for (int n = t; n < NSAMP; n += 1024) atomicAdd(&scnt[attrs[n]], 1);
    __syncthreads();
    if (t == 0) {
        int o = 0, co = 0;
        for (int a = 0; a < NATTR; a++) {
            soff[a] = o;
            g_offsets[a] = o;
            g_counts[a] = scnt[a];
            g_chunk_off[a] = co;
            o += scnt[a];
            co += (scnt[a] + GM2 - 1) / GM2;
        }
        g_chunk_off[NATTR] = co;
        g_nrow = NROW2 + scnt[5] + scnt[6];
    }
    if (t < NATTR) scur[t] = 0;
    __syncthreads();
    const int off5 = soff[5];
    for (int n = t; n < NSAMP; n += 1024) {
        int a = attrs[n];
        int p = atomicAdd(&scur[a], 1);
        int pos = soff[a] + p;
        g_idx[pos] = n;
        if (a >= 5) g_row2[n] = NROW2 + (pos - off5);
        out[n * 2 + 0] = b2[a * 2 + 0];
        out[n * 2 + 1] = b2[a * 2 + 1];
    }
}

// ---------------- prep kernels ----------------
__global__ void k_prep_img(const float* __restrict__ img) {
    const int CPR = IMG_DIM / 4;
    int idx = blockIdx.x * blockDim.x + threadIdx.x;
    if (idx >= M1 * CPR) return;
    int row = idx / CPR;
    if (row >= g_nrow) return;
    int c = idx - row * CPR;
    int n, s;
    if (row < NROW2) { n = row >> 1; s = row & 1; }
    else             { n = g_idx[g_offsets[5] + (row - NROW2)]; s = 2; }
    float4 v = *(const float4*)(img + (size_t)(n * MAX_IN + s) * IMG_DIM + c * 4);
    *(uint2*)(g_af + (size_t)row * IMG_DIM + c * 4) = pack4h(v);
}
#define WCNN_Q (IMG_DIM * FC / 4)
#define W1_Q (NATTR * 2 * FC * FC / 4)
__global__ void k_prep_w(const float* __restrict__ Wcnn,
                         const float* __restrict__ W1) {
    int idx = blockIdx.x * blockDim.x + threadIdx.x;
    if (idx < WCNN_Q) {
        float4 v = *(const float4*)(Wcnn + (size_t)idx * 4);
        *(uint2*)(g_wh + (size_t)idx * 4) = pack4h(v);
    } else if (idx < WCNN_Q + W1_Q) {
        int j = idx - WCNN_Q;
        float4 v = *(const float4*)(W1 + (size_t)j * 4);
        *(uint2*)(g_w1h + (size_t)j * 4) = pack4h(v);
    }
}

// -------- shared inner-tile compute: pipelined LDSM/MMA over one stage ------
// af regs reused across mt halves; bf double-buffered across ks.
#define TILE_COMPUTE(s_, OFFA_, ASTR_)                                        \
    do {                                                                      \
        uint32_t bf[2][2][4];                                                 \
        _Pragma("unroll")                                                     \
        for (int np = 0; np < 2; np++)                                        \
            ldsm_x4_t(bf[0][np], (s_) + OFF_B                                 \
                      + ((b_row) * BSTRIDE + wn + np * 16 + b_cs) * 2);       \
        _Pragma("unroll")                                                     \
        for (int ks = 0; ks < 2; ks++) {                                      \
            const int kb = ks * 16;                                           \
            if (ks == 0) {                                                    \
                _Pragma("unroll")                                             \
                for (int np = 0; np < 2; np++)                                \
                    ldsm_x4_t(bf[1][np], (s_) + OFF_B                         \
                              + ((16 + b_row) * BSTRIDE + wn + np * 16 + b_cs) * 2); \
            }                                                                 \
            uint32_t af[2][4];                                                \
            ldsm_x4(af[0], (s_) + (OFFA_)                                     \
                    + ((wm + a_row) * (ASTR_) + kb + a_ks) * 2);              \
            ldsm_x4(af[1], (s_) + (OFFA_)                                     \
                    + ((wm + 16 + a_row) * (ASTR_) + kb + a_ks) * 2);         \
            _Pragma("unroll")                                                 \
            for (int mt = 0; mt < 2; mt++)                                    \
                _Pragma("unroll")                                             \
                for (int nt = 0; nt < 4; nt++)                                \
                    mma16816(acc[mt][nt], af[mt], &bf[ks][nt >> 1][(nt & 1) * 2]); \
            ldsm_x4(af[0], (s_) + (OFFA_)                                     \
                    + ((wm + 32 + a_row) * (ASTR_) + kb + a_ks) * 2);         \
            ldsm_x4(af[1], (s_) + (OFFA_)                                     \
                    + ((wm + 48 + a_row) * (ASTR_) + kb + a_ks) * 2);         \
            _Pragma("unroll")                                                 \
            for (int mt = 2; mt < 4; mt++)                                    \
                _Pragma("unroll")                                             \
                for (int nt = 0; nt < 4; nt++)                                \
                    mma16816(acc[mt][nt], af[mt - 2], &bf[ks][nt >> 1][(nt & 1) * 2]); \
        }                                                                     \
    } while (0)

// ---------------- GEMM1: feats = relu(imgC @ Wcnn + b), fp16 out -----------
__global__ __launch_bounds__(256, 2) void k_gemm1(const float* __restrict__ bias)
{
    const int bn0 = blockIdx.x * BN, bm0 = blockIdx.y * BM;
    if (bm0 >= g_nrow) return;

    extern __shared__ char smem[];
    const uint32_t sb = (uint32_t)__cvta_generic_to_shared(smem);
    const int tid = threadIdx.x, lane = tid & 31, warp = tid >> 5;
    const int wm = (warp >> 2) * 64, wn = (warp & 3) * 32;
    const int fr = lane >> 2, fc = (lane & 3) * 2;
    const int a_row = lane & 15, a_ks = (lane >> 4) * 8;
    const int b_row = (lane & 7) + ((lane >> 3) & 1) * 8, b_cs = (lane >> 4) * 8;

    const int ar0 = tid >> 2, ac0 = tid & 3;
    const int brow = tid >> 4, bc2 = tid & 15;
    const __half* sA0 = g_af + (size_t)(bm0 + ar0) * IMG_DIM + ac0 * 8;
    const __half* sA1 = g_af + (size_t)(bm0 + ar0 + 64) * IMG_DIM + ac0 * 8;
    const __half* sB  = g_wh + (size_t)brow * FC + bn0 + bc2 * 8;
    const uint32_t dA0 = (uint32_t)(ar0 * (ASTRIDE * 2) + ac0 * 16);
    const uint32_t dA1 = dA0 + 64 * (ASTRIDE * 2);
    const uint32_t dB0 = (uint32_t)(brow * (BSTRIDE * 2) + bc2 * 16);
    const uint32_t dB1 = dB0 + 16 * (BSTRIDE * 2);

    float acc[4][4][4];
#pragma unroll
    for (int mt = 0; mt < 4; mt++)
#pragma unroll
        for (int nt = 0; nt < 4; nt++)
#pragma unroll
            for (int i = 0; i < 4; i++) acc[mt][nt][i] = 0.f;

#define G1_ISSUE(t_) do {                                            \
        const uint32_t s_ = sb + ((t_) % NSTG) * STAGE;              \
        const int k0_ = (t_) * BK;                                   \
        cp16(s_ + OFF_A + dA0, sA0 + k0_);                           \
        cp16(s_ + OFF_A + dA1, sA1 + k0_);                           \
        cp16(s_ + OFF_B + dB0, sB + (size_t)k0_ * FC);               \
        cp16(s_ + OFF_B + dB1, sB + (size_t)(k0_ + 16) * FC);        \
        cp_commit();                                                 \
    } while (0)

    G1_ISSUE(0); G1_ISSUE(1); G1_ISSUE(2);

    for (int t = 0; t < KT1; t++) {
        if (t < KT1 - 2) cp_wait2();
        else if (t == KT1 - 2) cp_wait1();
        else cp_wait0();
        __syncthreads();
        if (t + 3 < KT1) G1_ISSUE(t + 3);

        const uint32_t s = sb + (t % NSTG) * STAGE;
        TILE_COMPUTE(s, OFF_A, ASTRIDE);
    }

#pragma unroll
    for (int nt = 0; nt < 4; nt++) {
        int c = bn0 + wn + nt * 8 + fc;
        float b0 = __ldg(bias + c), b1v = __ldg(bias + c + 1);
#pragma unroll
        for (int mt = 0; mt < 4; mt++) {
            int r = bm0 + wm + mt * 16 + fr;
            __half2 h0 = __floats2half2_rn(fmaxf(acc[mt][nt][0] + b0, 0.f),
                                           fmaxf(acc[mt][nt][1] + b1v, 0.f));
            *(__half2*)(g_feats + (size_t)r * FC + c) = h0;
            __half2 h1 = __floats2half2_rn(fmaxf(acc[mt][nt][2] + b0, 0.f),
                                           fmaxf(acc[mt][nt][3] + b1v, 0.f));
            *(__half2*)(g_feats + (size_t)(r + 8) * FC + c) = h1;
        }
    }
#undef G1_ISSUE
}

// ---------------- build x (half2 vectorized) ----------------
__global__ void k_makex(const int* __restrict__ attrs) {
    int idx = blockIdx.x * blockDim.x + threadIdx.x;
    if (idx >= NSAMP * (FC / 2)) return;
    int n = idx / (FC / 2);
    int k = (idx - n * (FC / 2)) * 2;
    bool dist = (attrs[n] >= 5);
    __half2 f0 = *(const __half2*)(g_feats + (size_t)(2 * n) * FC + k);
    __half2 f1 = *(const __half2*)(g_feats + (size_t)(2 * n + 1) * FC + k);
    __half2 x0, x1;
    if (dist) {
        __half2 f2 = *(const __half2*)(g_feats + (size_t)g_row2[n] * FC + k);
        x0 = __hmul2(f0, f1);
        x1 = __hmul2(f1, f2);
    } else {
        x0 = f0;
        x1 = f1;
    }
    size_t base = (size_t)n * (2 * FC);
    *(__half2*)(g_xf + base + k)      = x0;
    *(__half2*)(g_xf + base + FC + k) = x1;
}

// ------- GEMM2 + fused scores: out += relu(x@W1+b1) @ W2[attr] -------------
__global__ __launch_bounds__(256, 2) void k_gemm2(
    const float* __restrict__ b1, const float* __restrict__ W2,
    float* __restrict__ out)
{
    const int y = blockIdx.y;
    if (y >= g_chunk_off[NATTR]) return;
    int attr = 0;
#pragma unroll
    for (int a = 0; a < NATTR; a++)
        if (y >= g_chunk_off[a]) attr = a;
    const int chunk = y - g_chunk_off[attr];
    const int cnt = g_counts[attr];
    const int base = g_offsets[attr] + chunk * GM2;
    const int nvalid = min(GM2, cnt - chunk * GM2);

    extern __shared__ char smem[];
    __shared__ int sid[GM2];
    const uint32_t sb = (uint32_t)__cvta_generic_to_shared(smem);
    const int tid = threadIdx.x, lane = tid & 31, warp = tid >> 5;
    const int bn0 = blockIdx.x * BN;
    const int wm = (warp >> 2) * 64, wn = (warp & 3) * 32;
    const int fr = lane >> 2, fc = (lane & 3) * 2;
    const int a_row = lane & 15, a_ks = (lane >> 4) * 8;
    const int b_row = (lane & 7) + ((lane >> 3) & 1) * 8, b_cs = (lane >> 4) * 8;

    if (tid < GM2) sid[tid] = (tid < nvalid) ? g_idx[base + tid] : -1;
    __syncthreads();

    const int ar0 = tid >> 2, ac0 = tid & 3;
    const int brow = tid >> 4, bc2 = tid & 15;
    const int s0 = sid[ar0], s1 = sid[ar0 + 64];
    const uint32_t asz0 = (s0 >= 0) ? 16u : 0u;
    const uint32_t asz1 = (s1 >= 0) ? 16u : 0u;
    const __half* sA0 = g_xf + (size_t)(s0 < 0 ? 0 : s0) * (2 * FC) + ac0 * 8;
    const __half* sA1 = g_xf + (size_t)(s1 < 0 ? 0 : s1) * (2 * FC) + ac0 * 8;
    const __half* sB  = g_w1h + (size_t)attr * 2 * FC * FC
                        + (size_t)brow * FC + bn0 + bc2 * 8;
    const uint32_t dA0 = (uint32_t)(ar0 * (ASTRIDE * 2) + ac0 * 16);
    const uint32_t dA1 = dA0 + 64 * (ASTRIDE * 2);
    const uint32_t dB0 = (uint32_t)(brow * (BSTRIDE * 2) + bc2 * 16);
    const uint32_t dB1 = dB0 + 16 * (BSTRIDE * 2);

    float acc[4][4][4];
#pragma unroll
    for (int mt = 0; mt < 4; mt++)
#pragma unroll
        for (int nt = 0; nt < 4; nt++)
#pragma unroll
            for (int i = 0; i < 4; i++) acc[mt][nt][i] = 0.f;

#define G2_ISSUE(t_) do {                                            \
        const uint32_t s_ = sb + ((t_) % NSTG) * STAGE;              \
        const int k0_ = (t_) * BK;                                   \
        cp16z(s_ + OFF_A + dA0, sA0 + k0_, asz0);                    \
        cp16z(s_ + OFF_A + dA1, sA1 + k0_, asz1);                    \
        cp16(s_ + OFF_B + dB0, sB + (size_t)k0_ * FC);               \
        cp16(s_ + OFF_B + dB1, sB + (size_t)(k0_ + 16) * FC);        \
        cp_commit();                                                 \
    } while (0)

    G2_ISSUE(0); G2_ISSUE(1); G2_ISSUE(2);

    for (int t = 0; t < KT2; t++) {
        if (t < KT2 - 2) cp_wait2();
        else if (t == KT2 - 2) cp_wait1();
        else cp_wait0();
        __syncthreads();
        if (t + 3 < KT2) G2_ISSUE(t + 3);

        const uint32_t s = sb + (t % NSTG) * STAGE;
        TILE_COMPUTE(s, OFF_A, ASTRIDE);
    }

    // fused epilogue: h = relu(acc + b1); out[n] += h . W2[attr]
    const float* w2 = W2 + (size_t)attr * FC * NANS;
    const float* b1p = b1 + (size_t)attr * FC;
#pragma unroll
    for (int mt = 0; mt < 4; mt++) {
        float r0s0 = 0.f, r0s1 = 0.f, r1s0 = 0.f, r1s1 = 0.f;
#pragma unroll
        for (int nt = 0; nt < 4; nt++) {
            int c = bn0 + wn + nt * 8 + fc;
            float b0 = __ldg(b1p + c), bv = __ldg(b1p + c + 1);
            float w00 = __ldg(w2 + c * 2 + 0), w01 = __ldg(w2 + c * 2 + 1);
            float w10 = __ldg(w2 + c * 2 + 2), w11 = __ldg(w2 + c * 2 + 3);
            float h00 = fmaxf(acc[mt][nt][0] + b0, 0.f);
            float h01 = fmaxf(acc[mt][nt][1] + bv, 0.f);
            r0s0 += h00 * w00 + h01 * w10;
            r0s1 += h00 * w01 + h01 * w11;
            float h10 = fmaxf(acc[mt][nt][2] + b0, 0.f);
            float h11 = fmaxf(acc[mt][nt][3] + bv, 0.f);
            r1s0 += h10 * w00 + h11 * w10;
            r1s1 += h10 * w01 + h11 * w11;
        }
#pragma unroll
        for (int o = 1; o <= 2; o <<= 1) {
            r0s0 += __shfl_xor_sync(0xffffffffu, r0s0, o);
            r0s1 += __shfl_xor_sync(0xffffffffu, r0s1, o);
            r1s0 += __shfl_xor_sync(0xffffffffu, r1s0, o);
            r1s1 += __shfl_xor_sync(0xffffffffu, r1s1, o);
        }
        if ((lane & 3) == 0) {
            int rA = wm + mt * 16 + fr;
            int sA2 = sid[rA], sB2 = sid[rA + 8];
            if (sA2 >= 0) {
                atomicAdd(out + sA2 * 2 + 0, r0s0);
                atomicAdd(out + sA2 * 2 + 1, r0s1);
            }
            if (sB2 >= 0) {
                atomicAdd(out + sB2 * 2 + 0, r1s0);
                atomicAdd(out + sB2 * 2 + 1, r1s1);
            }
        }
    }
#undef G2_ISSUE
}

// ---------------- launch ----------------
extern "C" void kernel_launch(void* const* d_in, const int* in_sizes, int n_in,
                              void* d_out, int out_size) {
    const float* img   = (const float*)d_in[0];
    const int*   attrs = (const int*)d_in[1];
    const float* Wcnn  = (const float*)d_in[2];
    const float* bcnn  = (const float*)d_in[3];
    const float* W1    = (const float*)d_in[4];
    const float* b1    = (const float*)d_in[5];
    const float* W2    = (const float*)d_in[6];
    const float* b2    = (const float*)d_in[7];
    float* out = (float*)d_out;

    cudaFuncSetAttribute(k_gemm1, cudaFuncAttributeMaxDynamicSharedMemorySize, SMEM_SZ);
    cudaFuncSetAttribute(k_gemm2, cudaFuncAttributeMaxDynamicSharedMemorySize, SMEM_SZ);

    // slot 1..3: sort(+out init) + prep, slot 4: GEMM1 (ncu capture slot)
    k_sort<<<1, 1024>>>(attrs, b2, out);
    k_prep_img<<<(M1 * (IMG_DIM / 4) + 255) / 256, 256>>>(img);
    k_prep_w<<<(WCNN_Q + W1_Q + 255) / 256, 256>>>(Wcnn, W1);

    k_gemm1<<<dim3(FC / BN, M1 / BM), 256, SMEM_SZ>>>(bcnn);

    k_makex<<<(NSAMP * (FC / 2) + 255) / 256, 256>>>(attrs);

    k_gemm2<<<dim3(FC / BN, MAXCH), 256, SMEM_SZ>>>(b1, W2, out);
}

// round 16
// speedup vs baseline: 1.0143x; 1.0143x over previous
#include <cuda_runtime.h>
#include <cuda_fp16.h>
#include <stdint.h>

#define NSAMP 8192
#define MAX_IN 8
#define IMG_DIM 3200
#define FC 512
#define NATTR 7
#define NANS 2
#define M1 (NSAMP * 3)
#define NROW2 (2 * NSAMP)

// Common tiling: 128x128 block, BK=32, 256 thr (8 warps = 2M x 4N of 64x32)
#define BM 128
#define BN 128
#define BK 32
#define KT1 (IMG_DIM / BK)         // 100
#define KT2 ((2 * FC) / BK)        // 32
#define ASTRIDE 40                 // fp16 elems per A smem row (80 B)
#define BSTRIDE 136                // fp16 elems per B smem row (272 B)

#define OFF_A  0
#define OFF_B  10240
#define STAGE  18944
#define NSTG   4
#define SMEM_SZ (NSTG * STAGE)     // 75776 -> 2 CTAs/SM

#define GM2 128
#define MAXCH (NSAMP / GM2 + NATTR)  // 71

// ---------------- scratch ----------------
__device__ __align__(16) __half g_af[(size_t)M1 * IMG_DIM];   // compact rows
__device__ __align__(16) __half g_wh[(size_t)IMG_DIM * FC];
__device__ __align__(16) __half g_w1h[(size_t)NATTR * 2 * FC * FC];
__device__ __align__(16) __half g_xf[(size_t)NSAMP * 2 * FC];
__device__ __align__(16) __half g_feats[(size_t)M1 * FC];
__device__ int g_counts[NATTR];
__device__ int g_offsets[NATTR];
__device__ int g_chunk_off[NATTR + 1];
__device__ int g_idx[NSAMP];
__device__ int g_row2[NSAMP];
__device__ int g_nrow;

// ---------------- helpers ----------------
__device__ __forceinline__ uint2 pack4h(float4 v) {
    __half2 a = __floats2half2_rn(v.x, v.y);
    __half2 b = __floats2half2_rn(v.z, v.w);
    uint2 r;
    r.x = *(uint32_t*)&a;
    r.y = *(uint32_t*)&b;
    return r;
}
__device__ __forceinline__ void mma16816(float* c, const uint32_t* a, const uint32_t* b) {
    asm("mma.sync.aligned.m16n8k16.row.col.f32.f16.f16.f32 "
        "{%0,%1,%2,%3}, {%4,%5,%6,%7}, {%8,%9}, {%0,%1,%2,%3};\n"
        : "+f"(c[0]), "+f"(c[1]), "+f"(c[2]), "+f"(c[3])
        : "r"(a[0]), "r"(a[1]), "r"(a[2]), "r"(a[3]), "r"(b[0]), "r"(b[1]));
}
__device__ __forceinline__ void ldsm_x4(uint32_t* r, uint32_t a) {
    asm volatile("ldmatrix.sync.aligned.m8n8.x4.shared.b16 {%0,%1,%2,%3}, [%4];"
                 : "=r"(r[0]), "=r"(r[1]), "=r"(r[2]), "=r"(r[3]) : "r"(a));
}
__device__ __forceinline__ void ldsm_x4_t(uint32_t* r, uint32_t a) {
    asm volatile("ldmatrix.sync.aligned.m8n8.x4.trans.shared.b16 {%0,%1,%2,%3}, [%4];"
                 : "=r"(r[0]), "=r"(r[1]), "=r"(r[2]), "=r"(r[3]) : "r"(a));
}
__device__ __forceinline__ void cp16(uint32_t dst, const void* src) {
    asm volatile("cp.async.cg.shared.global [%0], [%1], 16;"
                 :: "r"(dst), "l"(src) : "memory");
}
__device__ __forceinline__ void cp16z(uint32_t dst, const void* src, uint32_t sz) {
    asm volatile("cp.async.cg.shared.global [%0], [%1], 16, %2;"
                 :: "r"(dst), "l"(src), "r"(sz) : "memory");
}
__device__ __forceinline__ void cp_commit() {
    asm volatile("cp.async.commit_group;" ::: "memory");
}
__device__ __forceinline__ void cp_wait2() {
    asm volatile("cp.async.wait_group 2;" ::: "memory");
}
__device__ __forceinline__ void cp_wait1() {
    asm volatile("cp.async.wait_group 1;" ::: "memory");
}
__device__ __forceinline__ void cp_wait0() {
    asm volatile("cp.async.wait_group 0;" ::: "memory");
}

// ---------------- fused sort + output init ----------------
__global__ void k_sort(const int* __restrict__ attrs,
                       const float* __restrict__ b2,
                       float* __restrict__ out) {
    __shared__ int scnt[NATTR], scur[NATTR], soff[NATTR];
    const int t = threadIdx.x;
    if (t < NATTR) scnt[t] = 0;
    __syncthreads();
    for (int n = t; n < NSAMP; n += 1024) atomicAdd(&scnt[attrs[n]], 1);
    __syncthreads();
    if (t == 0) {
        int o = 0, co = 0;
        for (int a = 0; a < NATTR; a++) {
            soff[a] = o;
            g_offsets[a] = o;
            g_counts[a] = scnt[a];
            g_chunk_off[a] = co;
            o += scnt[a];
            co += (scnt[a] + GM2 - 1) / GM2;
        }
        g_chunk_off[NATTR] = co;
        g_nrow = NROW2 + scnt[5] + scnt[6];
    }
    if (t < NATTR) scur[t] = 0;
    __syncthreads();
    const int off5 = soff[5];
    for (int n = t; n < NSAMP; n += 1024) {
        int a = attrs[n];
        int p = atomicAdd(&scur[a], 1);
        int pos = soff[a] + p;
        g_idx[pos] = n;
        if (a >= 5) g_row2[n] = NROW2 + (pos - off5);
        out[n * 2 + 0] = b2[a * 2 + 0];
        out[n * 2 + 1] = b2[a * 2 + 1];
    }
}

// ---------------- prep kernels ----------------
__global__ void k_prep_img(const float* __restrict__ img) {
    const int CPR = IMG_DIM / 4;
    int idx = blockIdx.x * blockDim.x + threadIdx.x;
    if (idx >= M1 * CPR) return;
    int row = idx / CPR;
    if (row >= g_nrow) return;
    int c = idx - row * CPR;
    int n, s;
    if (row < NROW2) { n = row >> 1; s = row & 1; }
    else             { n = g_idx[g_offsets[5] + (row - NROW2)]; s = 2; }
    float4 v = *(const float4*)(img + (size_t)(n * MAX_IN + s) * IMG_DIM + c * 4);
    *(uint2*)(g_af + (size_t)row * IMG_DIM + c * 4) = pack4h(v);
}
#define WCNN_Q (IMG_DIM * FC / 4)
#define W1_Q (NATTR * 2 * FC * FC / 4)
__global__ void k_prep_w(const float* __restrict__ Wcnn,
                         const float* __restrict__ W1) {
    int idx = blockIdx.x * blockDim.x + threadIdx.x;
    if (idx < WCNN_Q) {
        float4 v = *(const float4*)(Wcnn + (size_t)idx * 4);
        *(uint2*)(g_wh + (size_t)idx * 4) = pack4h(v);
    } else if (idx < WCNN_Q + W1_Q) {
        int j = idx - WCNN_Q;
        float4 v = *(const float4*)(W1 + (size_t)j * 4);
        *(uint2*)(g_w1h + (size_t)j * 4) = pack4h(v);
    }
}

// ---------------- GEMM1: feats = relu(imgC @ Wcnn + b), fp16 out -----------
__global__ __launch_bounds__(256, 2) void k_gemm1(const float* __restrict__ bias)
{
    const int bn0 = blockIdx.x * BN, bm0 = blockIdx.y * BM;
    if (bm0 >= g_nrow) return;

    extern __shared__ char smem[];
    const uint32_t sb = (uint32_t)__cvta_generic_to_shared(smem);
    const int tid = threadIdx.x, lane = tid & 31, warp = tid >> 5;
    const int wm = (warp >> 2) * 64, wn = (warp & 3) * 32;
    const int fr = lane >> 2, fc = (lane & 3) * 2;
    const int a_row = lane & 15, a_ks = (lane >> 4) * 8;
    const int b_row = (lane & 7) + ((lane >> 3) & 1) * 8, b_cs = (lane >> 4) * 8;

    const int ar0 = tid >> 2, ac0 = tid & 3;
    const int brow = tid >> 4, bc2 = tid & 15;
    const __half* sA0 = g_af + (size_t)(bm0 + ar0) * IMG_DIM + ac0 * 8;
    const __half* sA1 = g_af + (size_t)(bm0 + ar0 + 64) * IMG_DIM + ac0 * 8;
    const __half* sB  = g_wh + (size_t)brow * FC + bn0 + bc2 * 8;
    const uint32_t dA0 = (uint32_t)(ar0 * (ASTRIDE * 2) + ac0 * 16);
    const uint32_t dA1 = dA0 + 64 * (ASTRIDE * 2);
    const uint32_t dB0 = (uint32_t)(brow * (BSTRIDE * 2) + bc2 * 16);
    const uint32_t dB1 = dB0 + 16 * (BSTRIDE * 2);

    float acc[4][4][4];
#pragma unroll
    for (int mt = 0; mt < 4; mt++)
#pragma unroll
        for (int nt = 0; nt < 4; nt++)
#pragma unroll
            for (int i = 0; i < 4; i++) acc[mt][nt][i] = 0.f;

#define G1_ISSUE(t_) do {                                            \
        const uint32_t s_ = sb + ((t_) % NSTG) * STAGE;              \
        const int k0_ = (t_) * BK;                                   \
        cp16(s_ + OFF_A + dA0, sA0 + k0_);                           \
        cp16(s_ + OFF_A + dA1, sA1 + k0_);                           \
        cp16(s_ + OFF_B + dB0, sB + (size_t)k0_ * FC);               \
        cp16(s_ + OFF_B + dB1, sB + (size_t)(k0_ + 16) * FC);        \
        cp_commit();                                                 \
    } while (0)

    G1_ISSUE(0); G1_ISSUE(1); G1_ISSUE(2);

    for (int t = 0; t < KT1; t++) {
        if (t < KT1 - 2) cp_wait2();
        else if (t == KT1 - 2) cp_wait1();
        else cp_wait0();
        __syncthreads();
        if (t + 3 < KT1) G1_ISSUE(t + 3);

        const uint32_t s = sb + (t % NSTG) * STAGE;
#pragma unroll
        for (int ks = 0; ks < 2; ks++) {
            const int kb = ks * 16;
            uint32_t af[4][4], bf[2][4];
#pragma unroll
            for (int mt = 0; mt < 4; mt++)
                ldsm_x4(af[mt], s + OFF_A
                        + ((wm + mt * 16 + a_row) * ASTRIDE + kb + a_ks) * 2);
#pragma unroll
            for (int np = 0; np < 2; np++)
                ldsm_x4_t(bf[np], s + OFF_B
                          + ((kb + b_row) * BSTRIDE + wn + np * 16 + b_cs) * 2);
#pragma unroll
            for (int mt = 0; mt < 4; mt++)
#pragma unroll
                for (int nt = 0; nt < 4; nt++)
                    mma16816(acc[mt][nt], af[mt], &bf[nt >> 1][(nt & 1) * 2]);
        }
    }

    // epilogue: bias + relu -> fp16 feats
#pragma unroll
    for (int nt = 0; nt < 4; nt++) {
        int c = bn0 + wn + nt * 8 + fc;
        float b0 = __ldg(bias + c), b1v = __ldg(bias + c + 1);
#pragma unroll
        for (int mt = 0; mt < 4; mt++) {
            int r = bm0 + wm + mt * 16 + fr;
            __half2 h0 = __floats2half2_rn(fmaxf(acc[mt][nt][0] + b0, 0.f),
                                           fmaxf(acc[mt][nt][1] + b1v, 0.f));
            *(__half2*)(g_feats + (size_t)r * FC + c) = h0;
            __half2 h1 = __floats2half2_rn(fmaxf(acc[mt][nt][2] + b0, 0.f),
                                           fmaxf(acc[mt][nt][3] + b1v, 0.f));
            *(__half2*)(g_feats + (size_t)(r + 8) * FC + c) = h1;
        }
    }
#undef G1_ISSUE
}

// ---------------- build x (half2 vectorized) ----------------
__global__ void k_makex(const int* __restrict__ attrs) {
    int idx = blockIdx.x * blockDim.x + threadIdx.x;
    if (idx >= NSAMP * (FC / 2)) return;
    int n = idx / (FC / 2);
    int k = (idx - n * (FC / 2)) * 2;
    bool dist = (attrs[n] >= 5);
    __half2 f0 = *(const __half2*)(g_feats + (size_t)(2 * n) * FC + k);
    __half2 f1 = *(const __half2*)(g_feats + (size_t)(2 * n + 1) * FC + k);
    __half2 x0, x1;
    if (dist) {
        __half2 f2 = *(const __half2*)(g_feats + (size_t)g_row2[n] * FC + k);
        x0 = __hmul2(f0, f1);
        x1 = __hmul2(f1, f2);
    } else {
        x0 = f0;
        x1 = f1;
    }
    size_t base = (size_t)n * (2 * FC);
    *(__half2*)(g_xf + base + k)      = x0;
    *(__half2*)(g_xf + base + FC + k) = x1;
}

// ------- GEMM2 + fused scores: out += relu(x@W1+b1) @ W2[attr] -------------
__global__ __launch_bounds__(256, 2) void k_gemm2(
    const float* __restrict__ b1, const float* __restrict__ W2,
    float* __restrict__ out)
{
    const int y = blockIdx.y;
    if (y >= g_chunk_off[NATTR]) return;
    int attr = 0;
#pragma unroll
    for (int a = 0; a < NATTR; a++)
        if (y >= g_chunk_off[a]) attr = a;
    const int chunk = y - g_chunk_off[attr];
    const int cnt = g_counts[attr];
    const int base = g_offsets[attr] + chunk * GM2;
    const int nvalid = min(GM2, cnt - chunk * GM2);

    extern __shared__ char smem[];
    __shared__ int sid[GM2];
    const uint32_t sb = (uint32_t)__cvta_generic_to_shared(smem);
    const int tid = threadIdx.x, lane = tid & 31, warp = tid >> 5;
    const int bn0 = blockIdx.x * BN;
    const int wm = (warp >> 2) * 64, wn = (warp & 3) * 32;
    const int fr = lane >> 2, fc = (lane & 3) * 2;
    const int a_row = lane & 15, a_ks = (lane >> 4) * 8;
    const int b_row = (lane & 7) + ((lane >> 3) & 1) * 8, b_cs = (lane >> 4) * 8;

    if (tid < GM2) sid[tid] = (tid < nvalid) ? g_idx[base + tid] : -1;
    __syncthreads();

    const int ar0 = tid >> 2, ac0 = tid & 3;
    const int brow = tid >> 4, bc2 = tid & 15;
    const int s0 = sid[ar0], s1 = sid[ar0 + 64];
    const uint32_t asz0 = (s0 >= 0) ? 16u : 0u;
    const uint32_t asz1 = (s1 >= 0) ? 16u : 0u;
    const __half* sA0 = g_xf + (size_t)(s0 < 0 ? 0 : s0) * (2 * FC) + ac0 * 8;
    const __half* sA1 = g_xf + (size_t)(s1 < 0 ? 0 : s1) * (2 * FC) + ac0 * 8;
    const __half* sB  = g_w1h + (size_t)attr * 2 * FC * FC
                        + (size_t)brow * FC + bn0 + bc2 * 8;
    const uint32_t dA0 = (uint32_t)(ar0 * (ASTRIDE * 2) + ac0 * 16);
    const uint32_t dA1 = dA0 + 64 * (ASTRIDE * 2);
    const uint32_t dB0 = (uint32_t)(brow * (BSTRIDE * 2) + bc2 * 16);
    const uint32_t dB1 = dB0 + 16 * (BSTRIDE * 2);

    float acc[4][4][4];
#pragma unroll
    for (int mt = 0; mt < 4; mt++)
#pragma unroll
        for (int nt = 0; nt < 4; nt++)
#pragma unroll
            for (int i = 0; i < 4; i++) acc[mt][nt][i] = 0.f;

#define G2_ISSUE(t_) do {                                            \
        const uint32_t s_ = sb + ((t_) % NSTG) * STAGE;              \
        const int k0_ = (t_) * BK;                                   \
        cp16z(s_ + OFF_A + dA0, sA0 + k0_, asz0);                    \
        cp16z(s_ + OFF_A + dA1, sA1 + k0_, asz1);                    \
        cp16(s_ + OFF_B + dB0, sB + (size_t)k0_ * FC);               \
        cp16(s_ + OFF_B + dB1, sB + (size_t)(k0_ + 16) * FC);        \
        cp_commit();                                                 \
    } while (0)

    G2_ISSUE(0); G2_ISSUE(1); G2_ISSUE(2);

    for (int t = 0; t < KT2; t++) {
        if (t < KT2 - 2) cp_wait2();
        else if (t == KT2 - 2) cp_wait1();
        else cp_wait0();
        __syncthreads();
        if (t + 3 < KT2) G2_ISSUE(t + 3);

        const uint32_t s = sb + (t % NSTG) * STAGE;
#pragma unroll
        for (int ks = 0; ks < 2; ks++) {
            const int kb = ks * 16;
            uint32_t af[4][4], bf[2][4];
#pragma unroll
            for (int mt = 0; mt < 4; mt++)
                ldsm_x4(af[mt], s + OFF_A
                        + ((wm + mt * 16 + a_row) * ASTRIDE + kb + a_ks) * 2);
#pragma unroll
            for (int np = 0; np < 2; np++)
                ldsm_x4_t(bf[np], s + OFF_B
                          + ((kb + b_row) * BSTRIDE + wn + np * 16 + b_cs) * 2);
#pragma unroll
            for (int mt = 0; mt < 4; mt++)
#pragma unroll
                for (int nt = 0; nt < 4; nt++)
                    mma16816(acc[mt][nt], af[mt], &bf[nt >> 1][(nt & 1) * 2]);
        }
    }

    // fused epilogue: h = relu(acc + b1); out[n] += h . W2[attr]
    const float* w2 = W2 + (size_t)attr * FC * NANS;
    const float* b1p = b1 + (size_t)attr * FC;
#pragma unroll
    for (int mt = 0; mt < 4; mt++) {
        float r0s0 = 0.f, r0s1 = 0.f, r1s0 = 0.f, r1s1 = 0.f;
#pragma unroll
        for (int nt = 0; nt < 4; nt++) {
            int c = bn0 + wn + nt * 8 + fc;
            float b0 = __ldg(b1p + c), bv = __ldg(b1p + c + 1);
            float w00 = __ldg(w2 + c * 2 + 0), w01 = __ldg(w2 + c * 2 + 1);
            float w10 = __ldg(w2 + c * 2 + 2), w11 = __ldg(w2 + c * 2 + 3);
            float h00 = fmaxf(acc[mt][nt][0] + b0, 0.f);
            float h01 = fmaxf(acc[mt][nt][1] + bv, 0.f);
            r0s0 += h00 * w00 + h01 * w10;
            r0s1 += h00 * w01 + h01 * w11;
            float h10 = fmaxf(acc[mt][nt][2] + b0, 0.f);
            float h11 = fmaxf(acc[mt][nt][3] + bv, 0.f);
            r1s0 += h10 * w00 + h11 * w10;
            r1s1 += h10 * w01 + h11 * w11;
        }
#pragma unroll
        for (int o = 1; o <= 2; o <<= 1) {
            r0s0 += __shfl_xor_sync(0xffffffffu, r0s0, o);
            r0s1 += __shfl_xor_sync(0xffffffffu, r0s1, o);
            r1s0 += __shfl_xor_sync(0xffffffffu, r1s0, o);
            r1s1 += __shfl_xor_sync(0xffffffffu, r1s1, o);
        }
        if ((lane & 3) == 0) {
            int rA = wm + mt * 16 + fr;
            int sA2 = sid[rA], sB2 = sid[rA + 8];
            if (sA2 >= 0) {
                atomicAdd(out + sA2 * 2 + 0, r0s0);
                atomicAdd(out + sA2 * 2 + 1, r0s1);
            }
            if (sB2 >= 0) {
                atomicAdd(out + sB2 * 2 + 0, r1s0);
                atomicAdd(out + sB2 * 2 + 1, r1s1);
            }
        }
    }
#undef G2_ISSUE
}

// ---------------- launch ----------------
extern "C" void kernel_launch(void* const* d_in, const int* in_sizes, int n_in,
                              void* d_out, int out_size) {
    const float* img   = (const float*)d_in[0];
    const int*   attrs = (const int*)d_in[1];
    const float* Wcnn  = (const float*)d_in[2];
    const float* bcnn  = (const float*)d_in[3];
    const float* W1    = (const float*)d_in[4];
    const float* b1    = (const float*)d_in[5];
    const float* W2    = (const float*)d_in[6];
    const float* b2    = (const float*)d_in[7];
    float* out = (float*)d_out;

    cudaFuncSetAttribute(k_gemm1, cudaFuncAttributeMaxDynamicSharedMemorySize, SMEM_SZ);
    cudaFuncSetAttribute(k_gemm2, cudaFuncAttributeMaxDynamicSharedMemorySize, SMEM_SZ);

    // slot 1..3: sort(+out init) + prep, slot 4: GEMM1 (ncu capture slot)
    k_sort<<<1, 1024>>>(attrs, b2, out);
    k_prep_img<<<(M1 * (IMG_DIM / 4) + 255) / 256, 256>>>(img);
    k_prep_w<<<(WCNN_Q + W1_Q + 255) / 256, 256>>>(Wcnn, W1);

    k_gemm1<<<dim3(FC / BN, M1 / BM), 256, SMEM_SZ>>>(bcnn);

    k_makex<<<(NSAMP * (FC / 2) + 255) / 256, 256>>>(attrs);

    k_gemm2<<<dim3(FC / BN, MAXCH), 256, SMEM_SZ>>>(b1, W2, out);
}